// round 1
// baseline (speedup 1.0000x reference)
#include <cuda_runtime.h>
#include <math.h>

#define NB 16
#define HW 3136
#define CC 256
#define OH 224
#define OW 224
#define RR 16
#define KS 33
#define NOUT (NB*OH*OW)

__device__ float g_mask56[NB * HW];
__device__ float g_resized[NOUT];
__device__ float g_tmp[NOUT];

// ---------------------------------------------------------------------------
// Kernel 1: per-pixel Mahalanobis distance.
// One block per pixel p (3136 blocks x 256 threads).
// sd[c][b] = diff transposed in SMEM so pairs of batches load as LDS.64.
// Thread t owns column t of M_p: partial(t) = d_b[t] * sum_i M[i][t] d_b[i].
// f32x2 packed FMA: 2 batches per 64-bit accumulator, 8 accumulators.
// ---------------------------------------------------------------------------
__global__ __launch_bounds__(256, 4) void maha_kernel(
    const float* __restrict__ x, const float* __restrict__ mean,
    const float* __restrict__ M) {
  const int p = blockIdx.x;
  const int t = threadIdx.x;
  __shared__ float sd[CC][NB];
  __shared__ float red[8][NB];

  {
    const float mu = mean[p * CC + t];
    const float* xp = x + (size_t)p * CC + t;
#pragma unroll
    for (int b = 0; b < NB; b++)
      sd[t][b] = xp[(size_t)b * ((size_t)HW * CC)] - mu;
  }
  __syncthreads();

  unsigned long long acc[8];
#pragma unroll
  for (int k = 0; k < 8; k++) acc[k] = 0ull;  // {0.0f, 0.0f}

  const float* Mcol = M + ((size_t)p << 16) + t;

#pragma unroll 1
  for (int i0 = 0; i0 < CC; i0 += 16) {
    float m[16];
#pragma unroll
    for (int u = 0; u < 16; u++) m[u] = Mcol[(i0 + u) * CC];  // front-batched LDGs (MLP=16)
#pragma unroll
    for (int u = 0; u < 16; u++) {
      unsigned long long m2;
      asm("mov.b64 %0, {%1, %1};" : "=l"(m2) : "f"(m[u]));
      const unsigned long long* dp =
          reinterpret_cast<const unsigned long long*>(&sd[i0 + u][0]);
#pragma unroll
      for (int k = 0; k < 8; k++) {
        asm("fma.rn.f32x2 %0, %1, %2, %0;"
            : "+l"(acc[k])
            : "l"(m2), "l"(dp[k]));
      }
    }
  }

  float q[NB];
#pragma unroll
  for (int k = 0; k < 8; k++) {
    float lo, hi;
    asm("mov.b64 {%0, %1}, %2;" : "=f"(lo), "=f"(hi) : "l"(acc[k]));
    q[2 * k]     = lo * sd[t][2 * k];
    q[2 * k + 1] = hi * sd[t][2 * k + 1];
  }
#pragma unroll
  for (int b = 0; b < NB; b++) {
#pragma unroll
    for (int off = 16; off > 0; off >>= 1)
      q[b] += __shfl_down_sync(0xffffffffu, q[b], off);
  }
  const int warp = t >> 5, lane = t & 31;
  if (lane == 0) {
#pragma unroll
    for (int b = 0; b < NB; b++) red[warp][b] = q[b];
  }
  __syncthreads();
  if (t < NB) {
    float s = 0.f;
#pragma unroll
    for (int w = 0; w < 8; w++) s += red[w][t];
    g_mask56[t * HW + p] = sqrtf(fmaxf(s, 0.f));
  }
}

// ---------------------------------------------------------------------------
// Kernel 2: bilinear 56 -> 224 (half-pixel centers, clamp == jax edge renorm
// for pure upsampling).
// ---------------------------------------------------------------------------
__global__ void resize_kernel() {
  const int idx = blockIdx.x * blockDim.x + threadIdx.x;
  if (idx >= NOUT) return;
  const int xo = idx % OW;
  const int yo = (idx / OW) % OH;
  const int b = idx / (OW * OH);
  const float fy = (yo + 0.5f) * 0.25f - 0.5f;
  const float fx = (xo + 0.5f) * 0.25f - 0.5f;
  const int y0 = (int)floorf(fy);
  const int x0 = (int)floorf(fx);
  const float wy = fy - (float)y0;
  const float wx = fx - (float)x0;
  const int y0c = min(max(y0, 0), 55), y1c = min(max(y0 + 1, 0), 55);
  const int x0c = min(max(x0, 0), 55), x1c = min(max(x0 + 1, 0), 55);
  const float* mp = g_mask56 + b * HW;
  const float v00 = mp[y0c * 56 + x0c];
  const float v01 = mp[y0c * 56 + x1c];
  const float v10 = mp[y1c * 56 + x0c];
  const float v11 = mp[y1c * 56 + x1c];
  const float v = (1.f - wy) * ((1.f - wx) * v00 + wx * v01) +
                  wy * ((1.f - wx) * v10 + wx * v11);
  g_resized[idx] = v;
}

__device__ __forceinline__ int reflect101(int i) {
  if (i < 0) i = -i;
  if (i > 223) i = 446 - i;
  return i;
}

// Compute unnormalized Gaussian weights once per block into SMEM.
__device__ __forceinline__ void load_weights(float* w, float* inv) {
  const int tid = threadIdx.x;
  if (tid < KS) {
    const float d = (float)(tid - RR);
    w[tid] = expf(-(d * d) / 32.0f);  // 2*sigma^2 = 32
  }
  __syncthreads();
  if (tid == 0) {
    float s = 0.f;
    for (int j = 0; j < KS; j++) s += w[j];
    *inv = 1.0f / s;
  }
  __syncthreads();
}

// ---------------------------------------------------------------------------
// Kernel 3/4: separable Gaussian blur (vertical then horizontal), reflect-101.
// ---------------------------------------------------------------------------
__global__ void blur_v_kernel() {
  __shared__ float w[KS];
  __shared__ float inv;
  load_weights(w, &inv);
  const int idx = blockIdx.x * blockDim.x + threadIdx.x;
  if (idx >= NOUT) return;
  const int xo = idx % OW;
  const int yo = (idx / OW) % OH;
  const int b = idx / (OW * OH);
  const float* src = g_resized + b * OH * OW;
  float s = 0.f;
#pragma unroll
  for (int j = 0; j < KS; j++) {
    const int ry = reflect101(yo - RR + j);
    s += w[j] * src[ry * OW + xo];
  }
  g_tmp[idx] = s * inv;
}

__global__ void blur_h_kernel(float* __restrict__ out_mask) {
  __shared__ float w[KS];
  __shared__ float inv;
  load_weights(w, &inv);
  const int idx = blockIdx.x * blockDim.x + threadIdx.x;
  if (idx >= NOUT) return;
  const int xo = idx % OW;
  const int yo = (idx / OW) % OH;
  const int b = idx / (OW * OH);
  const float* src = g_tmp + (b * OH + yo) * OW;
  float s = 0.f;
#pragma unroll
  for (int j = 0; j < KS; j++) {
    const int rx = reflect101(xo - RR + j);
    s += w[j] * src[rx];
  }
  out_mask[idx] = s * inv;
}

// ---------------------------------------------------------------------------
// Kernel 5: per-batch max over blurred mask -> score.
// ---------------------------------------------------------------------------
__global__ void max_kernel(const float* __restrict__ mask,
                           float* __restrict__ score) {
  const int b = blockIdx.x;
  const float* mp = mask + b * OH * OW;
  float mx = -1e30f;
  for (int i = threadIdx.x; i < OH * OW; i += 256) mx = fmaxf(mx, mp[i]);
#pragma unroll
  for (int off = 16; off > 0; off >>= 1)
    mx = fmaxf(mx, __shfl_down_sync(0xffffffffu, mx, off));
  __shared__ float sm[8];
  if ((threadIdx.x & 31) == 0) sm[threadIdx.x >> 5] = mx;
  __syncthreads();
  if (threadIdx.x == 0) {
    float r = sm[0];
#pragma unroll
    for (int w = 1; w < 8; w++) r = fmaxf(r, sm[w]);
    score[b] = r;
  }
}

extern "C" void kernel_launch(void* const* d_in, const int* in_sizes, int n_in,
                              void* d_out, int out_size) {
  const float* inputs = (const float*)d_in[0];    // [16,56,56,256]
  const float* mean = (const float*)d_in[1];      // [3136,256]
  const float* cvar_inv = (const float*)d_in[2];  // [3136,256,256]
  float* out = (float*)d_out;
  float* score = out;          // [16,1]
  float* mask = out + NB;      // [16,224,224,1]

  maha_kernel<<<HW, 256>>>(inputs, mean, cvar_inv);
  const int nblk = (NOUT + 255) / 256;
  resize_kernel<<<nblk, 256>>>();
  blur_v_kernel<<<nblk, 256>>>();
  blur_h_kernel<<<nblk, 256>>>(mask);
  max_kernel<<<NB, 256>>>(mask, score);
}

// round 2
// speedup vs baseline: 1.3175x; 1.3175x over previous
#include <cuda_runtime.h>
#include <math.h>

#define NB 16
#define HW 3136
#define CC 256
#define OH 224
#define OW 224
#define RR 16
#define KS 33
#define NOUT (NB*OH*OW)

__device__ float g_mask56[NB * HW];
__device__ float g_resized[NOUT];
__device__ float g_tmp[NOUT];

// ---------------------------------------------------------------------------
// Kernel 1: per-pixel Mahalanobis distance, exploiting exact symmetry of M.
//   quad = sum_c d_c * (2 * S_c - M_cc * d_c),  S_c = sum_{i<=c} M_ic d_i
// One block per pixel (3136 x 256). Warp w owns column block cb (balanced
// mapping so each SMSP gets 288 rows total). Only rows [0, 32*(cb+1)) of M
// are read -> 56% of the matrix traffic. f32x2 FMAs, LDS.128 diff loads.
// ---------------------------------------------------------------------------
__global__ __launch_bounds__(256, 4) void maha_kernel(
    const float* __restrict__ x, const float* __restrict__ mean,
    const float* __restrict__ M) {
  const int p = blockIdx.x;
  const int t = threadIdx.x;
  const int wid = t >> 5, lane = t & 31;
  __shared__ float sd[CC][NB];   // transposed diff: sd[channel][batch]
  __shared__ float red[8][NB];

  {
    const float mu = mean[p * CC + t];
    const float* xp = x + (size_t)p * CC + t;
#pragma unroll
    for (int b = 0; b < NB; b++)
      sd[t][b] = xp[(size_t)b * ((size_t)HW * CC)] - mu;
  }
  __syncthreads();

  // SMSP-balanced column-block map: {7,0,6,1,5,2,4,3}
  const int cb = (wid & 1) ? (wid >> 1) : (7 - (wid >> 1));
  const int col = cb * 32 + lane;
  const float* Mc = M + ((size_t)p << 16) + col;
  const int nmain = cb * 32;  // rows with unconditional weight

  unsigned long long acc[8];
#pragma unroll
  for (int k = 0; k < 8; k++) acc[k] = 0ull;

  const unsigned sbase = (unsigned)__cvta_generic_to_shared(&sd[0][0]);

#pragma unroll 1
  for (int i0 = 0; i0 < nmain; i0 += 8) {
    float m[8];
#pragma unroll
    for (int u = 0; u < 8; u++) m[u] = Mc[(size_t)(i0 + u) * CC];
#pragma unroll
    for (int u = 0; u < 8; u++) {
      unsigned long long m2;
      asm("mov.b64 %0, {%1, %1};" : "=l"(m2) : "f"(m[u]));
      const unsigned ra = sbase + (i0 + u) * 64;
      unsigned long long d0, d1, d2, d3, d4, d5, d6, d7;
      asm("ld.shared.v2.u64 {%0,%1}, [%2];" : "=l"(d0), "=l"(d1) : "r"(ra));
      asm("ld.shared.v2.u64 {%0,%1}, [%2];" : "=l"(d2), "=l"(d3) : "r"(ra + 16));
      asm("ld.shared.v2.u64 {%0,%1}, [%2];" : "=l"(d4), "=l"(d5) : "r"(ra + 32));
      asm("ld.shared.v2.u64 {%0,%1}, [%2];" : "=l"(d6), "=l"(d7) : "r"(ra + 48));
      asm("fma.rn.f32x2 %0, %1, %2, %0;" : "+l"(acc[0]) : "l"(m2), "l"(d0));
      asm("fma.rn.f32x2 %0, %1, %2, %0;" : "+l"(acc[1]) : "l"(m2), "l"(d1));
      asm("fma.rn.f32x2 %0, %1, %2, %0;" : "+l"(acc[2]) : "l"(m2), "l"(d2));
      asm("fma.rn.f32x2 %0, %1, %2, %0;" : "+l"(acc[3]) : "l"(m2), "l"(d3));
      asm("fma.rn.f32x2 %0, %1, %2, %0;" : "+l"(acc[4]) : "l"(m2), "l"(d4));
      asm("fma.rn.f32x2 %0, %1, %2, %0;" : "+l"(acc[5]) : "l"(m2), "l"(d5));
      asm("fma.rn.f32x2 %0, %1, %2, %0;" : "+l"(acc[6]) : "l"(m2), "l"(d6));
      asm("fma.rn.f32x2 %0, %1, %2, %0;" : "+l"(acc[7]) : "l"(m2), "l"(d7));
    }
  }

  // Tail: 32 rows [nmain, nmain+32); row nmain+r contributes iff r <= lane.
#pragma unroll 1
  for (int r0 = 0; r0 < 32; r0 += 8) {
    float m[8];
#pragma unroll
    for (int u = 0; u < 8; u++) m[u] = Mc[(size_t)(nmain + r0 + u) * CC];
#pragma unroll
    for (int u = 0; u < 8; u++) {
      const float mv = ((r0 + u) <= lane) ? m[u] : 0.0f;
      unsigned long long m2;
      asm("mov.b64 %0, {%1, %1};" : "=l"(m2) : "f"(mv));
      const unsigned ra = sbase + (nmain + r0 + u) * 64;
      unsigned long long d0, d1, d2, d3, d4, d5, d6, d7;
      asm("ld.shared.v2.u64 {%0,%1}, [%2];" : "=l"(d0), "=l"(d1) : "r"(ra));
      asm("ld.shared.v2.u64 {%0,%1}, [%2];" : "=l"(d2), "=l"(d3) : "r"(ra + 16));
      asm("ld.shared.v2.u64 {%0,%1}, [%2];" : "=l"(d4), "=l"(d5) : "r"(ra + 32));
      asm("ld.shared.v2.u64 {%0,%1}, [%2];" : "=l"(d6), "=l"(d7) : "r"(ra + 48));
      asm("fma.rn.f32x2 %0, %1, %2, %0;" : "+l"(acc[0]) : "l"(m2), "l"(d0));
      asm("fma.rn.f32x2 %0, %1, %2, %0;" : "+l"(acc[1]) : "l"(m2), "l"(d1));
      asm("fma.rn.f32x2 %0, %1, %2, %0;" : "+l"(acc[2]) : "l"(m2), "l"(d2));
      asm("fma.rn.f32x2 %0, %1, %2, %0;" : "+l"(acc[3]) : "l"(m2), "l"(d3));
      asm("fma.rn.f32x2 %0, %1, %2, %0;" : "+l"(acc[4]) : "l"(m2), "l"(d4));
      asm("fma.rn.f32x2 %0, %1, %2, %0;" : "+l"(acc[5]) : "l"(m2), "l"(d5));
      asm("fma.rn.f32x2 %0, %1, %2, %0;" : "+l"(acc[6]) : "l"(m2), "l"(d6));
      asm("fma.rn.f32x2 %0, %1, %2, %0;" : "+l"(acc[7]) : "l"(m2), "l"(d7));
    }
  }

  const float Mcc = Mc[(size_t)col * CC];

  float q[NB];
#pragma unroll
  for (int k = 0; k < 8; k++) {
    float s0, s1;
    asm("mov.b64 {%0, %1}, %2;" : "=f"(s0), "=f"(s1) : "l"(acc[k]));
    const float dc0 = sd[col][2 * k];
    const float dc1 = sd[col][2 * k + 1];
    q[2 * k]     = dc0 * (2.0f * s0 - Mcc * dc0);
    q[2 * k + 1] = dc1 * (2.0f * s1 - Mcc * dc1);
  }
#pragma unroll
  for (int b = 0; b < NB; b++) {
#pragma unroll
    for (int off = 16; off > 0; off >>= 1)
      q[b] += __shfl_down_sync(0xffffffffu, q[b], off);
  }
  if (lane == 0) {
#pragma unroll
    for (int b = 0; b < NB; b++) red[wid][b] = q[b];
  }
  __syncthreads();
  if (t < NB) {
    float s = 0.f;
#pragma unroll
    for (int w = 0; w < 8; w++) s += red[w][t];
    g_mask56[t * HW + p] = sqrtf(fmaxf(s, 0.f));
  }
}

// ---------------------------------------------------------------------------
// Kernel 2: bilinear 56 -> 224 (half-pixel centers, clamp).
// ---------------------------------------------------------------------------
__global__ void resize_kernel() {
  const int idx = blockIdx.x * blockDim.x + threadIdx.x;
  if (idx >= NOUT) return;
  const int xo = idx % OW;
  const int yo = (idx / OW) % OH;
  const int b = idx / (OW * OH);
  const float fy = (yo + 0.5f) * 0.25f - 0.5f;
  const float fx = (xo + 0.5f) * 0.25f - 0.5f;
  const int y0 = (int)floorf(fy);
  const int x0 = (int)floorf(fx);
  const float wy = fy - (float)y0;
  const float wx = fx - (float)x0;
  const int y0c = min(max(y0, 0), 55), y1c = min(max(y0 + 1, 0), 55);
  const int x0c = min(max(x0, 0), 55), x1c = min(max(x0 + 1, 0), 55);
  const float* mp = g_mask56 + b * HW;
  const float v00 = mp[y0c * 56 + x0c];
  const float v01 = mp[y0c * 56 + x1c];
  const float v10 = mp[y1c * 56 + x0c];
  const float v11 = mp[y1c * 56 + x1c];
  const float v = (1.f - wy) * ((1.f - wx) * v00 + wx * v01) +
                  wy * ((1.f - wx) * v10 + wx * v11);
  g_resized[idx] = v;
}

__device__ __forceinline__ int reflect101(int i) {
  if (i < 0) i = -i;
  if (i > 223) i = 446 - i;
  return i;
}

__device__ __forceinline__ void load_weights(float* w, float* inv) {
  const int tid = threadIdx.x;
  if (tid < KS) {
    const float d = (float)(tid - RR);
    w[tid] = expf(-(d * d) / 32.0f);
  }
  __syncthreads();
  if (tid == 0) {
    float s = 0.f;
    for (int j = 0; j < KS; j++) s += w[j];
    *inv = 1.0f / s;
  }
}

// ---------------------------------------------------------------------------
// Kernel 3: vertical blur, SMEM column-strip tiling. grid = 16*7.
// Tile: 32 columns x (224+32) rows in SMEM, taps become LDS + FFMA.
// ---------------------------------------------------------------------------
__global__ __launch_bounds__(256) void blur_v_kernel() {
  __shared__ float s[OH + 32][32];  // 32 KB
  __shared__ float w[KS];
  __shared__ float inv;
  load_weights(w, &inv);
  const int tid = threadIdx.x;
  const int b = blockIdx.x / 7;
  const int xt = (blockIdx.x % 7) * 32;
  const float* src = g_resized + b * OH * OW + xt;
#pragma unroll
  for (int li = tid; li < (OH + 32) * 32; li += 256) {
    const int r = li >> 5, c = li & 31;
    const int gy = reflect101(r - RR);
    s[r][c] = src[gy * OW + c];
  }
  __syncthreads();
  float* dst = g_tmp + b * OH * OW + xt;
  const int c = tid & 31;
  for (int y = tid >> 5; y < OH; y += 8) {
    float sum = 0.f;
#pragma unroll
    for (int j = 0; j < KS; j++) sum += w[j] * s[y + j][c];
    dst[y * OW + c] = sum * inv;
  }
}

// ---------------------------------------------------------------------------
// Kernel 4: horizontal blur, SMEM row-strip tiling. grid = 16*7.
// Tile: 32 rows x (224+32) cols in SMEM.
// ---------------------------------------------------------------------------
__global__ __launch_bounds__(256) void blur_h_kernel(float* __restrict__ out_mask) {
  __shared__ float s[32][OW + 32];  // 32 KB (224+32 = 256 cols)
  __shared__ float w[KS];
  __shared__ float inv;
  load_weights(w, &inv);
  const int tid = threadIdx.x;
  const int b = blockIdx.x / 7;
  const int yt = (blockIdx.x % 7) * 32;
  const float* src = g_tmp + (b * OH + yt) * OW;
#pragma unroll
  for (int li = tid; li < 32 * 256; li += 256) {
    const int r = li >> 8, c = li & 255;
    const int gx = reflect101(c - RR);
    s[r][c] = src[r * OW + gx];
  }
  __syncthreads();
  float* dst = out_mask + (b * OH + yt) * OW;
  const int lane = tid & 31;
  for (int r = tid >> 5; r < 32; r += 8) {
    for (int x0 = 0; x0 < OW; x0 += 32) {
      const int x = x0 + lane;
      float sum = 0.f;
#pragma unroll
      for (int j = 0; j < KS; j++) sum += w[j] * s[r][x + j];
      dst[r * OW + x] = sum * inv;
    }
  }
}

// ---------------------------------------------------------------------------
// Kernel 5: per-batch max over blurred mask -> score.
// ---------------------------------------------------------------------------
__global__ void max_kernel(const float* __restrict__ mask,
                           float* __restrict__ score) {
  const int b = blockIdx.x;
  const float* mp = mask + b * OH * OW;
  float mx = -1e30f;
  for (int i = threadIdx.x; i < OH * OW; i += 256) mx = fmaxf(mx, mp[i]);
#pragma unroll
  for (int off = 16; off > 0; off >>= 1)
    mx = fmaxf(mx, __shfl_down_sync(0xffffffffu, mx, off));
  __shared__ float sm[8];
  if ((threadIdx.x & 31) == 0) sm[threadIdx.x >> 5] = mx;
  __syncthreads();
  if (threadIdx.x == 0) {
    float r = sm[0];
#pragma unroll
    for (int w = 1; w < 8; w++) r = fmaxf(r, sm[w]);
    score[b] = r;
  }
}

extern "C" void kernel_launch(void* const* d_in, const int* in_sizes, int n_in,
                              void* d_out, int out_size) {
  const float* inputs = (const float*)d_in[0];    // [16,56,56,256]
  const float* mean = (const float*)d_in[1];      // [3136,256]
  const float* cvar_inv = (const float*)d_in[2];  // [3136,256,256]
  float* out = (float*)d_out;
  float* score = out;          // [16,1]
  float* mask = out + NB;      // [16,224,224,1]

  maha_kernel<<<HW, 256>>>(inputs, mean, cvar_inv);
  const int nblk = (NOUT + 255) / 256;
  resize_kernel<<<nblk, 256>>>();
  blur_v_kernel<<<16 * 7, 256>>>();
  blur_h_kernel<<<16 * 7, 256>>>(mask);
  max_kernel<<<NB, 256>>>(mask, score);
}

// round 3
// speedup vs baseline: 1.3190x; 1.0011x over previous
#include <cuda_runtime.h>
#include <math.h>

#define NB 16
#define HW 3136
#define CC 256
#define OH 224
#define OW 224
#define RR 16
#define KS 33
#define NOUT (NB*OH*OW)

__device__ float g_mask56[NB * HW];
__device__ float g_tmp[NOUT];

// ---------------------------------------------------------------------------
// Kernel 1: per-pixel Mahalanobis distance, exploiting exact symmetry of M.
//   quad = sum_c d_c * (2 * S_c - M_cc * d_c),  S_c = sum_{i<=c} M_ic d_i
// One block per pixel (3136 x 256). Warp wid owns column block cb with
// SMSP-correct balance (SMSP = wid%4): cb = (wid<4) ? 7-wid : wid-4, so each
// wid%4 class processes exactly 288 rows. Rows beyond nmain are predicated
// per-lane (strict lower-triangle + diagonal). f32x2 FMAs, LDS.128 broadcasts.
// ---------------------------------------------------------------------------
__global__ __launch_bounds__(256, 4) void maha_kernel(
    const float* __restrict__ x, const float* __restrict__ mean,
    const float* __restrict__ M) {
  const int p = blockIdx.x;
  const int t = threadIdx.x;
  const int wid = t >> 5, lane = t & 31;
  __shared__ float sd[CC][NB];   // transposed diff: sd[channel][batch]
  __shared__ float red[8][NB];

  {
    const float mu = mean[p * CC + t];
    const float* xp = x + (size_t)p * CC + t;
#pragma unroll
    for (int b = 0; b < NB; b++)
      sd[t][b] = xp[(size_t)b * ((size_t)HW * CC)] - mu;
  }
  __syncthreads();

  // SMSP-balanced map: classes {wid, wid+4} sum to 288 rows each.
  const int cb = (wid < 4) ? (7 - wid) : (wid - 4);
  const int col = cb * 32 + lane;
  const float* Mc = M + ((size_t)p << 16) + col;
  const int nmain = cb * 32;          // rows with unconditional weight
  const int nrows = nmain + 32;       // total rows this warp touches

  unsigned long long acc[8];
#pragma unroll
  for (int k = 0; k < 8; k++) acc[k] = 0ull;

  const unsigned sbase = (unsigned)__cvta_generic_to_shared(&sd[0][0]);

#pragma unroll 1
  for (int i0 = 0; i0 < nrows; i0 += 8) {
    float m[8];
#pragma unroll
    for (int u = 0; u < 8; u++) m[u] = Mc[(size_t)(i0 + u) * CC];
#pragma unroll
    for (int u = 0; u < 8; u++) {
      // row contributes iff (i - nmain) <= lane (always true for i < nmain)
      const float mv = ((i0 + u - nmain) <= lane) ? m[u] : 0.0f;
      unsigned long long m2;
      asm("mov.b64 %0, {%1, %1};" : "=l"(m2) : "f"(mv));
      const unsigned ra = sbase + (i0 + u) * 64;
      unsigned long long d0, d1, d2, d3, d4, d5, d6, d7;
      asm("ld.shared.v2.u64 {%0,%1}, [%2];" : "=l"(d0), "=l"(d1) : "r"(ra));
      asm("ld.shared.v2.u64 {%0,%1}, [%2];" : "=l"(d2), "=l"(d3) : "r"(ra + 16));
      asm("ld.shared.v2.u64 {%0,%1}, [%2];" : "=l"(d4), "=l"(d5) : "r"(ra + 32));
      asm("ld.shared.v2.u64 {%0,%1}, [%2];" : "=l"(d6), "=l"(d7) : "r"(ra + 48));
      asm("fma.rn.f32x2 %0, %1, %2, %0;" : "+l"(acc[0]) : "l"(m2), "l"(d0));
      asm("fma.rn.f32x2 %0, %1, %2, %0;" : "+l"(acc[1]) : "l"(m2), "l"(d1));
      asm("fma.rn.f32x2 %0, %1, %2, %0;" : "+l"(acc[2]) : "l"(m2), "l"(d2));
      asm("fma.rn.f32x2 %0, %1, %2, %0;" : "+l"(acc[3]) : "l"(m2), "l"(d3));
      asm("fma.rn.f32x2 %0, %1, %2, %0;" : "+l"(acc[4]) : "l"(m2), "l"(d4));
      asm("fma.rn.f32x2 %0, %1, %2, %0;" : "+l"(acc[5]) : "l"(m2), "l"(d5));
      asm("fma.rn.f32x2 %0, %1, %2, %0;" : "+l"(acc[6]) : "l"(m2), "l"(d6));
      asm("fma.rn.f32x2 %0, %1, %2, %0;" : "+l"(acc[7]) : "l"(m2), "l"(d7));
    }
  }

  const float Mcc = Mc[(size_t)col * CC];

  float q[NB];
#pragma unroll
  for (int k = 0; k < 8; k++) {
    float s0, s1;
    asm("mov.b64 {%0, %1}, %2;" : "=f"(s0), "=f"(s1) : "l"(acc[k]));
    const float dc0 = sd[col][2 * k];
    const float dc1 = sd[col][2 * k + 1];
    q[2 * k]     = dc0 * (2.0f * s0 - Mcc * dc0);
    q[2 * k + 1] = dc1 * (2.0f * s1 - Mcc * dc1);
  }
#pragma unroll
  for (int b = 0; b < NB; b++) {
#pragma unroll
    for (int off = 16; off > 0; off >>= 1)
      q[b] += __shfl_down_sync(0xffffffffu, q[b], off);
  }
  if (lane == 0) {
#pragma unroll
    for (int b = 0; b < NB; b++) red[wid][b] = q[b];
  }
  __syncthreads();
  if (t < NB) {
    float s = 0.f;
#pragma unroll
    for (int w = 0; w < 8; w++) s += red[w][t];
    g_mask56[t * HW + p] = sqrtf(fmaxf(s, 0.f));
  }
}

__device__ __forceinline__ int reflect101(int i) {
  if (i < 0) i = -i;
  if (i > 223) i = 446 - i;
  return i;
}

__device__ __forceinline__ void load_weights(float* w, float* inv) {
  const int tid = threadIdx.x;
  if (tid < KS) {
    const float d = (float)(tid - RR);
    w[tid] = expf(-(d * d) / 32.0f);
  }
  __syncthreads();
  if (tid == 0) {
    float s = 0.f;
    for (int j = 0; j < KS; j++) s += w[j];
    *inv = 1.0f / s;
  }
}

// ---------------------------------------------------------------------------
// Kernel 2: FUSED bilinear resize (56->224, half-pixel, clamp) + vertical
// Gaussian blur. 16-wide column strips: grid = 16 * 14 = 224 blocks.
// SMEM tile padded to stride 17 to avoid 2-way bank conflicts.
// ---------------------------------------------------------------------------
__global__ __launch_bounds__(256) void blur_v_kernel() {
  __shared__ float s[OH + 32][17];
  __shared__ float w[KS];
  __shared__ float inv;
  load_weights(w, &inv);
  const int tid = threadIdx.x;
  const int b = blockIdx.x / 14;
  const int xt = (blockIdx.x % 14) * 16;
  const float* mp = g_mask56 + b * HW;
#pragma unroll
  for (int li = tid; li < (OH + 32) * 16; li += 256) {
    const int r = li >> 4, c = li & 15;
    const int gy = reflect101(r - RR);       // output-space row
    const int gx = xt + c;                   // output-space col
    // bilinear sample of the 56x56 map at output-space (gy, gx)
    const float fy = (gy + 0.5f) * 0.25f - 0.5f;
    const float fx = (gx + 0.5f) * 0.25f - 0.5f;
    const int y0 = (int)floorf(fy);
    const int x0 = (int)floorf(fx);
    const float wy = fy - (float)y0;
    const float wx = fx - (float)x0;
    const int y0c = min(max(y0, 0), 55), y1c = min(max(y0 + 1, 0), 55);
    const int x0c = min(max(x0, 0), 55), x1c = min(max(x0 + 1, 0), 55);
    const float v00 = mp[y0c * 56 + x0c];
    const float v01 = mp[y0c * 56 + x1c];
    const float v10 = mp[y1c * 56 + x0c];
    const float v11 = mp[y1c * 56 + x1c];
    s[r][c] = (1.f - wy) * ((1.f - wx) * v00 + wx * v01) +
              wy * ((1.f - wx) * v10 + wx * v11);
  }
  __syncthreads();
  float* dst = g_tmp + b * OH * OW + xt;
  const int c = tid & 15;
  for (int y = tid >> 4; y < OH; y += 16) {
    float sum = 0.f;
#pragma unroll
    for (int j = 0; j < KS; j++) sum += w[j] * s[y + j][c];
    dst[y * OW + c] = sum * inv;
  }
}

// ---------------------------------------------------------------------------
// Kernel 3: horizontal blur + per-batch max (atomicMax on nonneg float bits).
// 8-row strips: grid = 16 * 28 = 448 blocks.
// ---------------------------------------------------------------------------
__global__ __launch_bounds__(256) void blur_h_kernel(float* __restrict__ out_mask,
                                                     float* __restrict__ score) {
  __shared__ float s[8][256];
  __shared__ float w[KS];
  __shared__ float inv;
  __shared__ float smx[8];
  load_weights(w, &inv);
  const int tid = threadIdx.x;
  const int b = blockIdx.x / 28;
  const int yt = (blockIdx.x % 28) * 8;
  const float* src = g_tmp + (b * OH + yt) * OW;
#pragma unroll
  for (int li = tid; li < 8 * 256; li += 256) {
    const int r = li >> 8, c = li & 255;
    const int gx = reflect101(c - RR);
    s[r][c] = src[r * OW + gx];
  }
  __syncthreads();
  float* dst = out_mask + (b * OH + yt) * OW;
  const int lane = tid & 31;
  const int r = tid >> 5;
  float mx = 0.f;
#pragma unroll
  for (int x0 = 0; x0 < OW; x0 += 32) {
    const int x = x0 + lane;
    float sum = 0.f;
#pragma unroll
    for (int j = 0; j < KS; j++) sum += w[j] * s[r][x + j];
    sum *= inv;
    dst[r * OW + x] = sum;
    mx = fmaxf(mx, sum);
  }
#pragma unroll
  for (int off = 16; off > 0; off >>= 1)
    mx = fmaxf(mx, __shfl_down_sync(0xffffffffu, mx, off));
  if (lane == 0) smx[r] = mx;
  __syncthreads();
  if (tid == 0) {
    float m2 = smx[0];
#pragma unroll
    for (int k = 1; k < 8; k++) m2 = fmaxf(m2, smx[k]);
    // all values are >= 0 (sqrt outputs blurred with nonneg weights), so
    // integer compare on the bit pattern is order-preserving.
    atomicMax((int*)&score[b], __float_as_int(m2));
  }
}

__global__ void init_scores(float* score) {
  if (threadIdx.x < NB) score[threadIdx.x] = 0.0f;
}

extern "C" void kernel_launch(void* const* d_in, const int* in_sizes, int n_in,
                              void* d_out, int out_size) {
  const float* inputs = (const float*)d_in[0];    // [16,56,56,256]
  const float* mean = (const float*)d_in[1];      // [3136,256]
  const float* cvar_inv = (const float*)d_in[2];  // [3136,256,256]
  float* out = (float*)d_out;
  float* score = out;          // [16,1]
  float* mask = out + NB;      // [16,224,224,1]

  init_scores<<<1, 32>>>(score);
  maha_kernel<<<HW, 256>>>(inputs, mean, cvar_inv);
  blur_v_kernel<<<16 * 14, 256>>>();
  blur_h_kernel<<<16 * 28, 256>>>(mask, score);
}